// round 15
// baseline (speedup 1.0000x reference)
#include <cuda_runtime.h>
#include <cuda_bf16.h>
#include <math.h>
#include <stdint.h>

// Problem constants (B=1)
#define H_   8
#define S_   1024
#define D_   64
#define KG_  10

// Tiling
#define BI   64
#define BJ   64
#define NT   256
#define NSPLIT 2
#define TILES_PER_SPLIT (S_ / BJ / NSPLIT)

// LUT
#define LUTN    2048
#define RANGE_D 10.0f
#define RANGE_E 5.0f

// bf16 tile stride: 72 elements = 144 bytes; 144 = 9*16 -> cp.async 16B aligned;
// 36 words mod 32 == 4 -> every 8-lane ldmatrix phase conflict-free.
#define QS 72

__device__ float2 g_lutD[LUTN];
__device__ float2 g_lutE[LUTN];
__device__ float  g_vals[2][LUTN + 1];
// pre-split bf16 operands: per row, 64 hi || 64 lo  (256 bytes/row)
__device__ __nv_bfloat16 g_Qsp[H_ * S_ * 128];
__device__ __nv_bfloat16 g_Ksp[H_ * S_ * 128];
__device__ __nv_bfloat16 g_Vsp[H_ * S_ * 128];
// split-KV scratch (static __device__: no allocation)
__device__ float  g_Opart[NSPLIT][H_ * S_ * D_];
__device__ float2 g_ML[NSPLIT][H_ * S_];

// ---------------------------------------------------------------------------
// helpers
// ---------------------------------------------------------------------------
__device__ __forceinline__ void split_bf(float x, float& hi, float& lo) {
    __nv_bfloat16 h = __float2bfloat16_rn(x);
    hi = __bfloat162float(h);
    lo = x - hi;
}
__device__ __forceinline__ uint32_t pack_bf2(float a, float b) {
    __nv_bfloat162 t = __floats2bfloat162_rn(a, b);
    return *reinterpret_cast<uint32_t*>(&t);
}
__device__ __forceinline__ void mma_bf16(float* c, const uint32_t* a, const uint32_t* b) {
    asm volatile(
        "mma.sync.aligned.m16n8k16.row.col.f32.bf16.bf16.f32 "
        "{%0,%1,%2,%3}, {%4,%5,%6,%7}, {%8,%9}, {%0,%1,%2,%3};"
        : "+f"(c[0]), "+f"(c[1]), "+f"(c[2]), "+f"(c[3])
        : "r"(a[0]), "r"(a[1]), "r"(a[2]), "r"(a[3]), "r"(b[0]), "r"(b[1]));
}
__device__ __forceinline__ void ldsm_x4(uint32_t addr, uint32_t* r) {
    asm volatile("ldmatrix.sync.aligned.m8n8.x4.shared.b16 {%0,%1,%2,%3}, [%4];"
        : "=r"(r[0]), "=r"(r[1]), "=r"(r[2]), "=r"(r[3]) : "r"(addr));
}
__device__ __forceinline__ void ldsm_x4_trans(uint32_t addr, uint32_t* r) {
    asm volatile("ldmatrix.sync.aligned.m8n8.x4.trans.shared.b16 {%0,%1,%2,%3}, [%4];"
        : "=r"(r[0]), "=r"(r[1]), "=r"(r[2]), "=r"(r[3]) : "r"(addr));
}
__device__ __forceinline__ void cp_async16(uint32_t dst, const void* src) {
    asm volatile("cp.async.cg.shared.global [%0], [%1], 16;"
        :: "r"(dst), "l"(src) : "memory");
}
__device__ __forceinline__ void cp_async_commit_wait() {
    asm volatile("cp.async.commit_group;\ncp.async.wait_group 0;" ::: "memory");
}

// ---------------------------------------------------------------------------
// LUT construction
// ---------------------------------------------------------------------------
__device__ __forceinline__ float gelu_exact(float x) {
    return 0.5f * x * (1.0f + erff(x * 0.70710678118654752f));
}

__device__ float bias_eval(float x,
                           const float* __restrict__ mu, const float* __restrict__ sg,
                           const float* __restrict__ bb,
                           const float* __restrict__ W1, const float* __restrict__ b1,
                           const float* __restrict__ W2, float b2v) {
    float psi[KG_];
#pragma unroll
    for (int k = 0; k < KG_; k++) {
        float s = sg[k];
        float z = (x + bb[k] - mu[k]) / s;
        psi[k] = expf(-0.5f * z * z) * (0.3989422804014327f / s);
    }
    float acc = b2v;
#pragma unroll
    for (int l = 0; l < KG_; l++) {
        float hv = b1[l];
#pragma unroll
        for (int k = 0; k < KG_; k++) hv = fmaf(W1[l * KG_ + k], psi[k], hv);
        acc = fmaf(W2[l], gelu_exact(hv), acc);
    }
    return acc;
}

__global__ void build_vals_kernel(const float* __restrict__ muD, const float* __restrict__ sgD,
                                  const float* __restrict__ bD,
                                  const float* __restrict__ muE, const float* __restrict__ sgE,
                                  const float* __restrict__ bE,
                                  const float* __restrict__ W1, const float* __restrict__ b1,
                                  const float* __restrict__ W2, const float* __restrict__ b2) {
    int idx = blockIdx.x * blockDim.x + threadIdx.x;
    if (idx >= 2 * (LUTN + 1)) return;
    int which = idx / (LUTN + 1);
    int i = idx % (LUTN + 1);
    float b2v = b2[0];
    if (which == 0) {
        g_vals[0][i] = bias_eval((float)i * (RANGE_D / (float)LUTN), muD, sgD, bD, W1, b1, W2, b2v);
    } else {
        g_vals[1][i] = bias_eval((float)i * (RANGE_E / (float)LUTN), muE, sgE, bE, W1, b1, W2, b2v);
    }
}

__global__ void build_slopes_kernel() {
    int i = blockIdx.x * blockDim.x + threadIdx.x;
    if (i >= LUTN) return;
    float d0 = g_vals[0][i];
    g_lutD[i] = make_float2(d0, g_vals[0][i + 1] - d0);
    float e0 = g_vals[1][i];
    g_lutE[i] = make_float2(e0, g_vals[1][i + 1] - e0);
}

// ---------------------------------------------------------------------------
// Pre-split kernel: Q (scaled), K, V -> packed bf16 hi||lo rows (256 B/row).
// ---------------------------------------------------------------------------
__global__ __launch_bounds__(256) void presplit_kernel(
    const float* __restrict__ Qg, const float* __restrict__ Kg, const float* __restrict__ Vg) {
    int idx = blockIdx.x * blockDim.x + threadIdx.x;   // over H_*S_*16
    if (idx >= H_ * S_ * 16) return;
    int cg = idx & 15;            // 4-float col group
    int row = idx >> 4;           // h*S + s
    const float qk_scale = 0.0883883476483184f;  // 1/sqrt(2*D)

    float4 q = *(const float4*)(Qg + (size_t)row * D_ + cg * 4);
    float4 kv = *(const float4*)(Kg + (size_t)row * D_ + cg * 4);
    float4 vv = *(const float4*)(Vg + (size_t)row * D_ + cg * 4);
    q.x *= qk_scale; q.y *= qk_scale; q.z *= qk_scale; q.w *= qk_scale;

    float h0, l0, h1, l1, h2, l2, h3, l3;
    uint2 w;
    split_bf(q.x, h0, l0); split_bf(q.y, h1, l1);
    split_bf(q.z, h2, l2); split_bf(q.w, h3, l3);
    w.x = pack_bf2(h0, h1); w.y = pack_bf2(h2, h3);
    *(uint2*)(g_Qsp + (size_t)row * 128 + cg * 4) = w;
    w.x = pack_bf2(l0, l1); w.y = pack_bf2(l2, l3);
    *(uint2*)(g_Qsp + (size_t)row * 128 + 64 + cg * 4) = w;

    split_bf(kv.x, h0, l0); split_bf(kv.y, h1, l1);
    split_bf(kv.z, h2, l2); split_bf(kv.w, h3, l3);
    w.x = pack_bf2(h0, h1); w.y = pack_bf2(h2, h3);
    *(uint2*)(g_Ksp + (size_t)row * 128 + cg * 4) = w;
    w.x = pack_bf2(l0, l1); w.y = pack_bf2(l2, l3);
    *(uint2*)(g_Ksp + (size_t)row * 128 + 64 + cg * 4) = w;

    split_bf(vv.x, h0, l0); split_bf(vv.y, h1, l1);
    split_bf(vv.z, h2, l2); split_bf(vv.w, h3, l3);
    w.x = pack_bf2(h0, h1); w.y = pack_bf2(h2, h3);
    *(uint2*)(g_Vsp + (size_t)row * 128 + cg * 4) = w;
    w.x = pack_bf2(l0, l1); w.y = pack_bf2(l2, l3);
    *(uint2*)(g_Vsp + (size_t)row * 128 + 64 + cg * 4) = w;
}

// ---------------------------------------------------------------------------
// Fused flash attention, split-bf16 mma + ldmatrix + cp.async staging.
// grid = (S/BI, H, NSPLIT), block = 256 = 8 warps.
// Warp w: rows [(w/2)*16,+16), cols [(w%2)*32,+32) of the 64x64 tile.
// ---------------------------------------------------------------------------
__device__ __forceinline__ float lut_interp(const float2* __restrict__ lut, float x, float scale) {
    float t = x * scale;
    int ix = (int)t;
    ix = max(0, min(ix, LUTN - 1));
    float f = t - (float)ix;
    float2 e = lut[ix];
    return fmaf(e.y, f, e.x);
}

__global__ __launch_bounds__(NT, 2) void attn_partial_kernel(
    const float* __restrict__ DMg, const float* __restrict__ EMg, const int* __restrict__ Mg) {
    extern __shared__ unsigned char smraw[];
    float2* lutD = (float2*)smraw;
    float2* lutE = lutD + LUTN;
    __nv_bfloat16* Qhi = (__nv_bfloat16*)(lutE + LUTN);   // [i][QS] (pre-scaled)
    __nv_bfloat16* Qlo = Qhi + BI * QS;
    __nv_bfloat16* Khi = Qlo + BI * QS;                   // [j][d]
    __nv_bfloat16* Klo = Khi + BJ * QS;
    __nv_bfloat16* Vhi = Klo + BJ * QS;                   // [j][d] natural (ldsm.trans)
    __nv_bfloat16* Vlo = Vhi + BJ * QS;
    __nv_bfloat16* Phi = Vlo + BJ * QS;                   // [i][j]
    __nv_bfloat16* Plo = Phi + BI * QS;
    float* redm = (float*)(Plo + BI * QS);                // [2][64]
    float* reds = redm + 2 * BI;                          // [2][64]

    const int tid = threadIdx.x;
    const int lane = tid & 31;
    const int warp = tid >> 5;
    const int qr = lane >> 2;
    const int qc = lane & 3;
    const int wr = warp >> 1;
    const int wc = warp & 1;

    const int h = blockIdx.y;
    const int i0 = blockIdx.x * BI;
    const int split = blockIdx.z;

    const float lscaleD = (float)LUTN / RANGE_D;
    const float lscaleE = (float)LUTN / RANGE_E;

    const uint32_t qhi_s = (uint32_t)__cvta_generic_to_shared(Qhi);
    const uint32_t qlo_s = (uint32_t)__cvta_generic_to_shared(Qlo);
    const uint32_t khi_s = (uint32_t)__cvta_generic_to_shared(Khi);
    const uint32_t klo_s = (uint32_t)__cvta_generic_to_shared(Klo);
    const uint32_t vhi_s = (uint32_t)__cvta_generic_to_shared(Vhi);
    const uint32_t vlo_s = (uint32_t)__cvta_generic_to_shared(Vlo);
    const uint32_t phi_s = (uint32_t)__cvta_generic_to_shared(Phi);
    const uint32_t plo_s = (uint32_t)__cvta_generic_to_shared(Plo);

    // ldmatrix per-lane address components (validated R10):
    const uint32_t aoff = (uint32_t)(((wr * 16 + (lane & 15)) * QS) * 2 + ((lane >> 4) << 4));
    const uint32_t bk_base = ((lane >> 4) ? klo_s : khi_s)
                           + (uint32_t)(((lane & 7) * QS) * 2 + (((lane >> 3) & 1) << 4));
    const uint32_t bv_base = ((lane >> 4) ? vlo_s : vhi_s)
                           + (uint32_t)(((lane & 15) * QS) * 2);

    // cp.async copy pattern: 16B chunk c (0..15) of 256B row; c<8 -> hi, else lo.
    const int st_row = tid >> 4;          // base row for this thread (0..15 step via +16)
    const int st_c = tid & 15;            // chunk
    const uint32_t st_dhi = (uint32_t)((st_c & 7) * 16);
    const bool st_ishi = (st_c < 8);

    // Stage LUTs
    for (int t = tid; t < LUTN; t += NT) lutD[t] = g_lutD[t];
    for (int t = tid; t < LUTN; t += NT) lutE[t] = g_lutE[t];

    // Stage Q tile via cp.async (4 chunks/thread)
    {
        const char* qsrc = (const char*)g_Qsp + ((size_t)(h * S_ + i0)) * 256;
#pragma unroll
        for (int k = 0; k < 4; k++) {
            int row = st_row + k * 16;
            uint32_t dst = (st_ishi ? qhi_s : qlo_s) + (uint32_t)(row * 144) + st_dhi;
            cp_async16(dst, qsrc + (size_t)row * 256 + st_c * 16);
        }
        cp_async_commit_wait();
    }

    float o[4][4];
#pragma unroll
    for (int cb = 0; cb < 4; cb++)
#pragma unroll
        for (int e = 0; e < 4; e++) o[cb][e] = 0.f;
    float m2[2] = {-1e30f, -1e30f};
    float l2a[2] = {0.f, 0.f};

    const int row0l = wr * 16 + qr;
    const int row1l = row0l + 8;

    for (int jt = 0; jt < TILES_PER_SPLIT; jt++) {
        const int j0 = (split * TILES_PER_SPLIT + jt) * BJ;

        __syncthreads();  // prev-tile consumers done

        // Stage K,V via cp.async (pure copy; 8 chunks/thread)
        {
            const char* ksrc = (const char*)g_Ksp + ((size_t)(h * S_ + j0)) * 256;
            const char* vsrc = (const char*)g_Vsp + ((size_t)(h * S_ + j0)) * 256;
#pragma unroll
            for (int k = 0; k < 4; k++) {
                int row = st_row + k * 16;
                uint32_t doff = (uint32_t)(row * 144) + st_dhi;
                cp_async16((st_ishi ? khi_s : klo_s) + doff, ksrc + (size_t)row * 256 + st_c * 16);
                cp_async16((st_ishi ? vhi_s : vlo_s) + doff, vsrc + (size_t)row * 256 + st_c * 16);
            }
        }

        // Bias + mask loads issue in the cp.async shadow
        float2 dm2[2][4], em2[2][4];
        int2 mk2[2][4];
        {
            size_t rbase0 = ((size_t)h * S_ + (i0 + row0l)) * S_ + j0;
            size_t rbase1 = ((size_t)h * S_ + (i0 + row1l)) * S_ + j0;
#pragma unroll
            for (int cb = 0; cb < 4; cb++) {
                int colg = (wc * 4 + cb) * 8 + qc * 2;
                dm2[0][cb] = *(const float2*)(DMg + rbase0 + colg);
                dm2[1][cb] = *(const float2*)(DMg + rbase1 + colg);
                em2[0][cb] = *(const float2*)(EMg + rbase0 + colg);
                em2[1][cb] = *(const float2*)(EMg + rbase1 + colg);
                mk2[0][cb] = *(const int2*)(Mg + rbase0 + colg);
                mk2[1][cb] = *(const int2*)(Mg + rbase1 + colg);
            }
        }

        cp_async_commit_wait();
        __syncthreads();  // tiles visible

        // ---- QK^T: ldmatrix + bf16 mma (3-term) ----
        float sc[4][4];
#pragma unroll
        for (int cb = 0; cb < 4; cb++)
#pragma unroll
            for (int e = 0; e < 4; e++) sc[cb][e] = 0.f;

#pragma unroll
        for (int kk = 0; kk < 4; kk++) {
            uint32_t ah[4], al[4];
            ldsm_x4(qhi_s + aoff + kk * 32, ah);
            ldsm_x4(qlo_s + aoff + kk * 32, al);
#pragma unroll
            for (int cb = 0; cb < 4; cb++) {
                uint32_t b[4];
                ldsm_x4(bk_base + (uint32_t)((wc * 4 + cb) * 8 * QS * 2) + kk * 32, b);
                mma_bf16(sc[cb], ah, b);
                mma_bf16(sc[cb], ah, b + 2);
                mma_bf16(sc[cb], al, b);
            }
        }

        // ---- LUT biases + mask ----
#pragma unroll
        for (int cb = 0; cb < 4; cb++) {
            float s0 = sc[cb][0] + lut_interp(lutD, dm2[0][cb].x, lscaleD)
                     + lut_interp(lutE, em2[0][cb].x, lscaleE);
            float s1 = sc[cb][1] + lut_interp(lutD, dm2[0][cb].y, lscaleD)
                     + lut_interp(lutE, em2[0][cb].y, lscaleE);
            float s2 = sc[cb][2] + lut_interp(lutD, dm2[1][cb].x, lscaleD)
                     + lut_interp(lutE, em2[1][cb].x, lscaleE);
            float s3 = sc[cb][3] + lut_interp(lutD, dm2[1][cb].y, lscaleD)
                     + lut_interp(lutE, em2[1][cb].y, lscaleE);
            sc[cb][0] = (mk2[0][cb].x == 0) ? -1e9f : s0;
            sc[cb][1] = (mk2[0][cb].y == 0) ? -1e9f : s1;
            sc[cb][2] = (mk2[1][cb].x == 0) ? -1e9f : s2;
            sc[cb][3] = (mk2[1][cb].y == 0) ? -1e9f : s3;
        }

        // ---- online softmax across the warp pair (smem reduce) ----
        float mxp[2];
#pragma unroll
        for (int r = 0; r < 2; r++) {
            int e0 = r * 2, e1 = e0 + 1;
            float v = fmaxf(fmaxf(sc[0][e0], sc[0][e1]), fmaxf(sc[1][e0], sc[1][e1]));
            v = fmaxf(v, fmaxf(fmaxf(sc[2][e0], sc[2][e1]), fmaxf(sc[3][e0], sc[3][e1])));
            v = fmaxf(v, __shfl_xor_sync(0xffffffffu, v, 1));
            v = fmaxf(v, __shfl_xor_sync(0xffffffffu, v, 2));
            mxp[r] = v;
            if (qc == 0) redm[wc * BI + ((r == 0) ? row0l : row1l)] = v;
        }

        __syncthreads();

        float corr2[2];
#pragma unroll
        for (int r = 0; r < 2; r++) {
            int e0 = r * 2, e1 = e0 + 1;
            int rowl = (r == 0) ? row0l : row1l;
            float mfull = fmaxf(mxp[r], redm[(1 - wc) * BI + rowl]);
            float mnew = fmaxf(m2[r], mfull);
            corr2[r] = __expf(m2[r] - mnew);
            m2[r] = mnew;
            float ps = 0.f;
#pragma unroll
            for (int cb = 0; cb < 4; cb++) {
                float p0 = __expf(sc[cb][e0] - mnew);
                float p1 = __expf(sc[cb][e1] - mnew);
                sc[cb][e0] = p0;
                sc[cb][e1] = p1;
                ps += p0 + p1;
            }
            ps += __shfl_xor_sync(0xffffffffu, ps, 1);
            ps += __shfl_xor_sync(0xffffffffu, ps, 2);
            if (qc == 0) reds[wc * BI + rowl] = ps;
#pragma unroll
            for (int cb = 0; cb < 4; cb++) {
                o[cb][e0] *= corr2[r];
                o[cb][e1] *= corr2[r];
                float h0, l0, h1, l1;
                split_bf(sc[cb][e0], h0, l0);
                split_bf(sc[cb][e1], h1, l1);
                int col = (wc * 4 + cb) * 8 + qc * 2;
                *(uint32_t*)(Phi + rowl * QS + col) = pack_bf2(h0, h1);
                *(uint32_t*)(Plo + rowl * QS + col) = pack_bf2(l0, l1);
            }
        }

        __syncthreads();  // sums + full P tile visible

#pragma unroll
        for (int r = 0; r < 2; r++) {
            int rowl = (r == 0) ? row0l : row1l;
            float total = reds[rowl] + reds[BI + rowl];
            l2a[r] = l2a[r] * corr2[r] + total;
        }

        // ---- O += P * V: ldmatrix(+trans for V) + bf16 mma (3-term) ----
#pragma unroll
        for (int kk = 0; kk < 4; kk++) {
            uint32_t ah[4], al[4];
            ldsm_x4(phi_s + aoff + kk * 32, ah);
            ldsm_x4(plo_s + aoff + kk * 32, al);
#pragma unroll
            for (int cb = 0; cb < 4; cb++) {
                uint32_t b[4];
                ldsm_x4_trans(bv_base + (uint32_t)(kk * 16 * QS * 2)
                              + (uint32_t)((wc * 32 + cb * 8) * 2), b);
                mma_bf16(o[cb], ah, b);
                mma_bf16(o[cb], ah, b + 2);
                mma_bf16(o[cb], al, b);
            }
        }
    }

    // ---- Epilogue: store un-normalized partial O + (m, l) ----
    float* Op = g_Opart[split];
    int ig0 = i0 + row0l;
    int ig1 = i0 + row1l;
#pragma unroll
    for (int cb = 0; cb < 4; cb++) {
        int dcol = (wc * 4 + cb) * 8 + qc * 2;
        *(float2*)(Op + ((size_t)h * S_ + ig0) * D_ + dcol) = make_float2(o[cb][0], o[cb][1]);
        *(float2*)(Op + ((size_t)h * S_ + ig1) * D_ + dcol) = make_float2(o[cb][2], o[cb][3]);
    }
    if (qc == 0 && wc == 0) {
        g_ML[split][h * S_ + ig0] = make_float2(m2[0], l2a[0]);
        g_ML[split][h * S_ + ig1] = make_float2(m2[1], l2a[1]);
    }
}

// ---------------------------------------------------------------------------
// Combine pass: merge NSPLIT partial softmax results. 2 rows per thread (MLP).
// ---------------------------------------------------------------------------
#define COMB_N (H_ * S_ * (D_ / 4))
__global__ __launch_bounds__(256) void combine_kernel(float* __restrict__ Og) {
    int idx0 = blockIdx.x * blockDim.x + threadIdx.x;
#pragma unroll
    for (int half = 0; half < 2; half++) {
        int idx = idx0 + half * (COMB_N / 2);
        int row = idx >> 4;          // D_/4 == 16
        int dcol = (idx & 15) * 4;

        float2 ml0 = g_ML[0][row];
        float2 ml1 = g_ML[1][row];
        float4 o0 = *(const float4*)&g_Opart[0][(size_t)row * D_ + dcol];
        float4 o1 = *(const float4*)&g_Opart[1][(size_t)row * D_ + dcol];

        float m = fmaxf(ml0.x, ml1.x);
        float a0 = __expf(ml0.x - m);
        float a1 = __expf(ml1.x - m);
        float inv = 1.0f / fmaf(ml0.y, a0, ml1.y * a1);

        float4 r;
        r.x = fmaf(o0.x, a0, o1.x * a1) * inv;
        r.y = fmaf(o0.y, a0, o1.y * a1) * inv;
        r.z = fmaf(o0.z, a0, o1.z * a1) * inv;
        r.w = fmaf(o0.w, a0, o1.w * a1) * inv;
        *(float4*)(Og + (size_t)row * D_ + dcol) = r;
    }
}

// ---------------------------------------------------------------------------
// kernel_launch
// Input order: Q, K, V, distance_matrix, energy_matrix, mask,
//              mu_D, sigma_D, b_D, mu_E, sigma_E, b_E, W1, b1, W2, b2
// ---------------------------------------------------------------------------
extern "C" void kernel_launch(void* const* d_in, const int* in_sizes, int n_in,
                              void* d_out, int out_size) {
    const float* Q  = (const float*)d_in[0];
    const float* K  = (const float*)d_in[1];
    const float* V  = (const float*)d_in[2];
    const float* DM = (const float*)d_in[3];
    const float* EM = (const float*)d_in[4];
    const int*   MK = (const int*)d_in[5];
    const float* muD = (const float*)d_in[6];
    const float* sgD = (const float*)d_in[7];
    const float* bD  = (const float*)d_in[8];
    const float* muE = (const float*)d_in[9];
    const float* sgE = (const float*)d_in[10];
    const float* bE  = (const float*)d_in[11];
    const float* W1  = (const float*)d_in[12];
    const float* b1  = (const float*)d_in[13];
    const float* W2  = (const float*)d_in[14];
    const float* b2  = (const float*)d_in[15];
    float* Og = (float*)d_out;

    const int smem_bytes = 2 * LUTN * (int)sizeof(float2)
                         + 8 * BI * QS * (int)sizeof(__nv_bfloat16)
                         + 4 * BI * (int)sizeof(float);

    cudaFuncSetAttribute(attn_partial_kernel, cudaFuncAttributeMaxDynamicSharedMemorySize, smem_bytes);

    int nev = 2 * (LUTN + 1);
    build_vals_kernel<<<(nev + 255) / 256, 256>>>(muD, sgD, bD, muE, sgE, bE, W1, b1, W2, b2);
    build_slopes_kernel<<<(LUTN + 255) / 256, 256>>>();
    presplit_kernel<<<(H_ * S_ * 16 + 255) / 256, 256>>>(Q, K, V);

    dim3 grid(S_ / BI, H_, NSPLIT);
    attn_partial_kernel<<<grid, NT, smem_bytes>>>(DM, EM, MK);

    combine_kernel<<<(COMB_N / 2 + 255) / 256, 256>>>(Og);
}